// round 4
// baseline (speedup 1.0000x reference)
#include <cuda_runtime.h>

#define CIN  64
#define HH   32
#define WW   32
#define COUT 128
#define NK   9

#define PSCALE   19.235933878f     // (1/(2*N_IDEAL*VT)) * log2(e)
#define CEXP     0.26359713812f    // 2^{-s_b2} = exp(-4/3)
#define B2LIN    3.8471867757f     // 2*s_b2
#define B2SQ     3.7002114715f     // s_b2^2
#define OSCALE_EFF 2.7025482e-5f   // ALPHA*R*ln2^2
#define ECLAMP   4.2535296e37f     // 2^125
#define ETH      3.269017e6f       // e^15 = 2^21.64 : tail switch
#define TSKIPE   0.00390625f       // 2^{-8} skip threshold

// per (co,cin): 9 elements {T=2^{-theta_s}, pk=x byte off} sorted by theta asc
// (T desc), packed as 5 float4 {T0,pk0,T1,pk1}... last = {T8,pk8,0,0}
__device__ float4 g_tab[COUT * CIN * 5];
// EX = 2^{x * PSCALE} per input pixel
__device__ float  g_ex[32 * CIN * HH * WW];

__device__ __forceinline__ float ex2a(float x) {
    float r; asm("ex2.approx.ftz.f32 %0, %1;" : "=f"(r) : "f"(x)); return r;
}
__device__ __forceinline__ float lg2a(float x) {
    float r; asm("lg2.approx.ftz.f32 %0, %1;" : "=f"(r) : "f"(x)); return r;
}

// ---------------- prepass 1: EX = 2^(x*PSCALE) ----------------
__global__ void k_ex(const float* __restrict__ x) {
    int i = blockIdx.x * 256 + threadIdx.x;
    if (i < 32 * CIN * HH * WW) g_ex[i] = ex2a(x[i] * PSCALE);
}

// ---------------- prepass 2: per-(co,cin) sort of 9 thetas ----------------
__global__ void k_sortT(const float* __restrict__ theta) {
    int i = blockIdx.x * 256 + threadIdx.x;   // 8192 bins
    if (i >= COUT * CIN) return;
    int co  = i / CIN;
    int cin = i - co * CIN;

    float th[9]; unsigned pk[9];
    #pragma unroll
    for (int kk = 0; kk < 9; ++kk) {
        th[kk] = theta[(co * CIN + cin) * NK + kk] * PSCALE;
        pk[kk] = (unsigned)(((cin & 15) * 204 + (kk / 3) * 34 + (kk % 3)) * 4);
    }
    // insertion sort ascending by theta
    for (int a = 1; a < 9; ++a) {
        float kt = th[a]; unsigned kp = pk[a];
        int j = a - 1;
        while (j >= 0 && th[j] > kt) { th[j+1] = th[j]; pk[j+1] = pk[j]; --j; }
        th[j+1] = kt; pk[j+1] = kp;
    }
    float4* dst = g_tab + i * 5;
    #pragma unroll
    for (int k = 0; k < 4; ++k)
        dst[k] = make_float4(ex2a(-th[2*k]),   __uint_as_float(pk[2*k]),
                             ex2a(-th[2*k+1]), __uint_as_float(pk[2*k+1]));
    dst[4] = make_float4(ex2a(-th[8]), __uint_as_float(pk[8]), 0.f, 0.f);
}

// ---------------- main ----------------
__device__ __forceinline__ float felem(float T, float pkf, const char* xc) {
    float ex = *(const float*)(xc + __float_as_uint(pkf));   // LDS, conflict-free
    float e  = fminf(ex * T, ECLAMP);                        // 2^z (clamped)
    float l1 = lg2a(1.f + e);
    float l2 = lg2a(fmaf(e, CEXP, 1.f));
    float g  = (l1 - l2) * (l1 + l2);
    return (e > ETH) ? fmaf(B2LIN, l1, -B2SQ) : g;           // l1 == z in tail range
}

#define WALK(ACC, P) do {                                    \
    const float4* _p = (P);                                  \
    _Pragma("unroll 1")                                      \
    for (int _k = 0; _k < 5; ++_k) {                         \
        float4 A = __ldg(_p + _k);                           \
        if (A.x <= TH) break;                                \
        ACC += felem(A.x, A.y, xc);                          \
        if (A.z <= TH) break;                                \
        ACC += felem(A.z, A.w, xc);                          \
    }                                                        \
} while (0)

__global__ void __launch_bounds__(128, 12)
k_main(float* __restrict__ out) {
    __shared__ float s_ex[16 * 204];   // EX tile: [16 cin][6 rows][34 cols]
    __shared__ float s_th[4 * 64];     // [warp][cin]: T threshold

    const int tid  = threadIdx.x;
    const int w    = tid >> 5;
    const int lane = tid & 31;
    const int r0   = blockIdx.x << 2;  // 8 row tiles * 4 rows
    const int b    = blockIdx.y;
    const int grp  = blockIdx.z;       // co group of 32

    const float* exb = g_ex + b * (CIN * HH * WW);
    const char*  xc  = (const char*)s_ex + (w * 34 + lane) * 4;

    #pragma unroll 1
    for (int cog = 0; cog < 8; ++cog) {          // 8 groups of 4 co
        const int co0 = grp * 32 + cog * 4;
        float acc0 = 0.f, acc1 = 0.f, acc2 = 0.f, acc3 = 0.f;

        #pragma unroll 1
        for (int ph = 0; ph < 4; ++ph) {         // 4 phases of 16 cin
            const int cb = ph << 4;

            __syncthreads();                     // prev readers done
            for (int idx = tid; idx < 16 * 204; idx += 128) {
                int cl  = idx / 204;
                int rem = idx - cl * 204;
                int rr  = rem / 34;
                int cc  = rem - rr * 34;
                int gr  = r0 - 1 + rr;
                int gc  = cc - 1;
                float v = 1.0f;                  // pad: x=0 -> 2^0
                if ((unsigned)gr < HH && (unsigned)gc < WW)
                    v = exb[(cb + cl) * (HH * WW) + gr * WW + gc];
                s_ex[idx] = v;
            }
            __syncthreads();

            if (cog == 0) {                      // thresholds once per phase
                for (int cl = 0; cl < 16; ++cl) {
                    const float* p = s_ex + cl * 204 + w * 34;
                    float m = fmaxf(fmaxf(p[lane], p[lane + 34]), p[lane + 68]);
                    if (lane < 2)
                        m = fmaxf(m, fmaxf(fmaxf(p[32 + lane], p[66 + lane]), p[100 + lane]));
                    #pragma unroll
                    for (int off = 16; off; off >>= 1)
                        m = fmaxf(m, __shfl_xor_sync(0xffffffffu, m, off));
                    if (lane == 0) s_th[w * 64 + cb + cl] = __fdividef(TSKIPE, m);
                }
                __syncwarp();
            }

            #pragma unroll 1
            for (int cl = 0; cl < 16; ++cl) {
                const float  TH = s_th[w * 64 + cb + cl];
                const float4* pb = g_tab + (co0 * CIN + cb + cl) * 5;
                WALK(acc0, pb);
                WALK(acc1, pb + CIN * 5);
                WALK(acc2, pb + 2 * CIN * 5);
                WALK(acc3, pb + 3 * CIN * 5);
            }
        }

        float* op = out + ((long)b * COUT + co0) * 1024 + (r0 + w) * 32 + lane;
        op[0]    = fminf(fmaxf(acc0 * OSCALE_EFF, 0.f), 9.f);
        op[1024] = fminf(fmaxf(acc1 * OSCALE_EFF, 0.f), 9.f);
        op[2048] = fminf(fmaxf(acc2 * OSCALE_EFF, 0.f), 9.f);
        op[3072] = fminf(fmaxf(acc3 * OSCALE_EFF, 0.f), 9.f);
    }
}

extern "C" void kernel_launch(void* const* d_in, const int* in_sizes, int n_in,
                              void* d_out, int out_size) {
    const float* xin   = (const float*)d_in[0];
    const float* theta = (const float*)d_in[1];
    if (n_in >= 2 && in_sizes[0] == COUT * CIN * NK) {  // defensive swap
        const float* t = xin; xin = theta; theta = t;
    }

    k_ex<<<(32 * CIN * HH * WW + 255) / 256, 256>>>(xin);
    k_sortT<<<(COUT * CIN + 255) / 256, 256>>>(theta);

    dim3 grid(8, 32, 4);
    k_main<<<grid, 128>>>((float*)d_out);
}

// round 5
// speedup vs baseline: 2.1606x; 2.1606x over previous
#include <cuda_runtime.h>

#define CIN  64
#define HH   32
#define WW   32
#define COUT 128
#define NK   9

#define PSCALE 19.235933878f          // (1/(2*N_IDEAL*VT)) * log2(e)
#define LSC    16.0f                  // LUT entries per base-2 z unit
#define XSC    (PSCALE * LSC)         // x pre-scale -> index units
#define TBIAS  128.0f                 // zlo = -8  ->  +8*16
#define CEXP   0.26359713812f         // 2^{-s_b2} = exp(-4/3)
#define OSCALE_EFF 2.7025482e-5f      // ALPHA*R*ln2^2
#define MAGIC  8388608.0f             // 2^23 floor trick

// 512 bins = (cin, co-group-of-16). 144 sorted float2 {t'=theta*XSC-TBIAS,
// pk=(co_l<<25)|x_byte_off} ascending by theta = 72 float4. +4 pad.
__device__ float4 g_tab[512 * 72 + 4];

__device__ __forceinline__ float ex2a(float x) {
    float r; asm("ex2.approx.ftz.f32 %0, %1;" : "=f"(r) : "f"(x)); return r;
}
__device__ __forceinline__ float lg2a(float x) {
    float r; asm("lg2.approx.ftz.f32 %0, %1;" : "=f"(r) : "f"(x)); return r;
}

// exact-enough r(z): softplus_b2(z)^2 - softplus_b2(z - s)^2   (b2^2 units)
__device__ __forceinline__ float rfun(float z) {
    float e  = ex2a(z);                       // z in [-8, 24.1]: no overflow
    float l1 = lg2a(1.f + e);
    float l2 = lg2a(fmaf(e, CEXP, 1.f));
    return (l1 - l2) * (l1 + l2);
}

// ---------------- prepass: per-(cin, co-group-of-16) bitonic sort ----------------
__global__ void __launch_bounds__(256) k_sort(const float* __restrict__ theta) {
    __shared__ float sk[256];
    __shared__ unsigned sv[256];
    const int bx  = blockIdx.x;          // 512 bins = cin*8 + grp
    const int cin = bx >> 3;
    const int grp = bx & 7;
    const int t   = threadIdx.x;

    float key = 1e30f;
    unsigned val = 0;
    if (t < 144) {
        int co_l = t / 9;                // 0..15
        int kk   = t - co_l * 9;
        int co   = grp * 16 + co_l;
        key = theta[(co * CIN + cin) * NK + kk] * XSC - TBIAS;
        unsigned xoff = (unsigned)(((cin & 15) * 204 + (kk / 3) * 34 + (kk % 3)) * 4);
        val = ((unsigned)co_l << 25) | xoff;   // pk>>16 = co_l*512 = acc byte off
    }
    sk[t] = key; sv[t] = val;
    __syncthreads();

    for (int ksz = 2; ksz <= 256; ksz <<= 1) {
        for (int j = ksz >> 1; j > 0; j >>= 1) {
            int ixj = t ^ j;
            if (ixj > t) {
                bool up = ((t & ksz) == 0);
                float a = sk[t], b = sk[ixj];
                if (up ? (a > b) : (a < b)) {
                    unsigned va = sv[t], vb = sv[ixj];
                    sk[t] = b; sk[ixj] = a;
                    sv[t] = vb; sv[ixj] = va;
                }
            }
            __syncthreads();
        }
    }

    if (t < 144) {
        float2* dst = (float2*)g_tab;
        dst[bx * 144 + t] = make_float2(sk[t], __uint_as_float(sv[t]));
    }
}

// ---------------- main ----------------
__device__ __forceinline__ void proc_elem(float tp, float pv,
                                          const char* __restrict__ xc,
                                          const char* __restrict__ lutc,
                                          char* __restrict__ accc) {
    unsigned pk = __float_as_uint(pv);
    float xp = *(const float*)(xc + (pk & 0xffffu));   // x' = x*XSC (LDS)
    float c  = fmaxf(xp - tp, 0.f);                    // index, lo-clamped
    float c2 = fminf(c, 511.f);
    float m  = c2 + MAGIC;                             // nearest-int anchor
    float fl = m - MAGIC;
    float fr = c - fl;                                 // frac (unclamped hi: tail)
    unsigned off = (__float_as_uint(m) & 0x1ffu) << 3; // entry * 8 bytes
    float2 lv = *(const float2*)(lutc + off);          // {value, secant slope}
    float r  = fmaf(lv.y, fr, lv.x);                   // linear interp / extrap
    float* a = (float*)(accc + (pk >> 16));            // private acc slot
    *a += r;
}

#define WALK4(P) do {                                          \
    proc_elem((P).x, (P).y, xc, lutc, accc);                   \
} while (0)

__global__ void __launch_bounds__(128, 8)
k_main(const float* __restrict__ x, float* __restrict__ out) {
    __shared__ float  s_ex[16 * 204];   // x' tile: [16 cin][6][34], *XSC, 0-pad
    __shared__ float  s_acc[16 * 128];  // [16 co][128 tid]
    __shared__ float2 s_lut[512];       // {r(z_i), r(z_{i+1})-r(z_i)}
    __shared__ float  s_th[4 * 16];     // [warp][cin_local]: window max of x'

    const int tid  = threadIdx.x;
    const int w    = tid >> 5;
    const int lane = tid & 31;
    const int r0   = blockIdx.x << 2;   // 8 row tiles * 4 rows
    const int b    = blockIdx.y;
    const int grp  = blockIdx.z;        // co group of 16

    // zero private accumulators
    #pragma unroll
    for (int c = 0; c < 16; ++c) s_acc[(c << 7) + tid] = 0.f;

    // build LUT (512 entries over z in [-8, 24), h = 1/16)
    for (int i = tid; i < 512; i += 128) {
        float z  = -8.f + (float)i * 0.0625f;
        float v0 = rfun(z);
        float v1 = rfun(z + 0.0625f);
        s_lut[i] = make_float2(v0, v1 - v0);
    }

    const float* xbase = x + b * (CIN * HH * WW);
    const char*  xc    = (const char*)s_ex + (w * 34 + lane) * 4;
    const char*  lutc  = (const char*)s_lut;
    char*        accc  = (char*)(s_acc + tid);

    #pragma unroll 1
    for (int ph = 0; ph < 4; ++ph) {
        const int cb = ph << 4;

        __syncthreads();                // prev phase readers done (also LUT/acc init)
        for (int idx = tid; idx < 16 * 204; idx += 128) {
            unsigned u = (unsigned)idx;
            int cl  = u / 204u;
            int rem = u - cl * 204u;
            int rr  = rem / 34u;
            int cc  = rem - rr * 34u;
            int gr  = r0 - 1 + rr;
            int gc  = cc - 1;
            float v = 0.f;
            if ((unsigned)gr < HH && (unsigned)gc < WW)
                v = xbase[(cb + cl) * (HH * WW) + gr * WW + gc] * XSC;
            s_ex[idx] = v;
        }
        __syncthreads();

        // per-(warp, cin_local) window max of x'
        for (int cl = 0; cl < 16; ++cl) {
            const float* p = s_ex + cl * 204 + w * 34;
            float m = fmaxf(fmaxf(p[lane], p[lane + 34]), p[lane + 68]);
            if (lane < 2)
                m = fmaxf(m, fmaxf(fmaxf(p[32 + lane], p[66 + lane]), p[100 + lane]));
            #pragma unroll
            for (int off = 16; off; off >>= 1)
                m = fmaxf(m, __shfl_xor_sync(0xffffffffu, m, off));
            if (lane == 0) s_th[w * 16 + cl] = m;
        }
        __syncwarp();

        // dense walk over sorted-live elements (break: t' >= window max -> z <= -8)
        #pragma unroll 1
        for (int cl = 0; cl < 16; ++cl) {
            const float   TH = s_th[w * 16 + cl];
            const float4* pp = g_tab + ((cb + cl) * 8 + grp) * 72;

            float4 A = __ldg(pp);
            float4 B = __ldg(pp + 1);
            #pragma unroll 1
            for (int i = 0; i < 72; i += 2) {
                if (A.x >= TH) break;            // warp-uniform
                float4 A2 = __ldg(pp + i + 2);   // prefetch (pad at table end)
                float4 B2 = __ldg(pp + i + 3);
                proc_elem(A.x, A.y, xc, lutc, accc);
                proc_elem(A.z, A.w, xc, lutc, accc);
                proc_elem(B.x, B.y, xc, lutc, accc);
                proc_elem(B.z, B.w, xc, lutc, accc);
                A = A2; B = B2;
            }
        }
    }

    // epilogue (own slots only; no sync needed)
    float* op = out + ((long)b * COUT + grp * 16) * 1024 + (r0 + w) * 32 + lane;
    #pragma unroll
    for (int c = 0; c < 16; ++c) {
        float v = s_acc[(c << 7) + tid] * OSCALE_EFF;
        op[c * 1024] = fminf(fmaxf(v, 0.f), 9.f);
    }
}

extern "C" void kernel_launch(void* const* d_in, const int* in_sizes, int n_in,
                              void* d_out, int out_size) {
    const float* xin   = (const float*)d_in[0];
    const float* theta = (const float*)d_in[1];
    if (n_in >= 2 && in_sizes[0] == COUT * CIN * NK) {  // defensive swap
        const float* t = xin; xin = theta; theta = t;
    }

    k_sort<<<512, 256>>>(theta);

    dim3 grid(8, 32, 8);
    k_main<<<grid, 128>>>(xin, (float*)d_out);
}